// round 5
// baseline (speedup 1.0000x reference)
#include <cuda_runtime.h>
#include <math.h>

#define NN 10000
#define EE 160000
#define TE 32
#define NHALF 512
#define THREADS 512

// shared memory layout (float offsets)
#define OFF_W2   0          // 64*512
#define OFF_W    32768      // 32*512
#define OFF_H    49152      // 2048 u64 (64 k x 32 e, duplicated pairs)
#define OFF_W1   53248      // 16*64
#define OFF_B1   54272      // 64
#define OFF_B2   54336      // 512
#define OFF_EMB  54848      // 16*32 transposed [k][e]
#define OFF_X    55360      // 32*64
#define OFF_SH   57408      // 32*4
#define OFF_SRC  57536      // 32 ints
#define OFF_DST  57568      // 32 ints
#define SMEM_FLOATS 57600
#define SMEM_BYTES (SMEM_FLOATS * 4)   // 230400 <= 232448 opt-in max

__device__ float g_agg[NN * 64];

static __device__ __forceinline__ unsigned long long pack_dup(float x) {
    unsigned long long r;
    asm("mov.b64 %0, {%1, %1};" : "=l"(r) : "f"(x));
    return r;
}
static __device__ __forceinline__ float2 unpack2(unsigned long long v) {
    float2 f;
    asm("mov.b64 {%0, %1}, %2;" : "=f"(f.x), "=f"(f.y) : "l"(v));
    return f;
}
#define FMA2(acc, a, b) asm("fma.rn.f32x2 %0, %1, %2, %0;" : "+l"(acc) : "l"(a), "l"(b))

__global__ void zero_kernel() {
    g_agg[blockIdx.x * 1024 + threadIdx.x] = 0.0f;
}

__global__ __launch_bounds__(THREADS, 1)
void edge_kernel(const float* __restrict__ nf,
                 const float* __restrict__ esh,
                 const float* __restrict__ emb,
                 const float* __restrict__ w1,
                 const float* __restrict__ b1,
                 const float* __restrict__ w2,
                 const float* __restrict__ b2,
                 const int*   __restrict__ eidx)
{
    extern __shared__ float sm[];
    float* sW2  = sm + OFF_W2;
    float* sW   = sm + OFF_W;
    unsigned long long* sHd = (unsigned long long*)(sm + OFF_H);
    float* sW1  = sm + OFF_W1;
    float* sB1  = sm + OFF_B1;
    float* sB2  = sm + OFF_B2;
    float* sEmbT= sm + OFF_EMB;
    float* sX   = sm + OFF_X;
    float* sSH  = sm + OFF_SH;
    int*   sSrc = (int*)(sm + OFF_SRC);
    int*   sDst = (int*)(sm + OFF_DST);

    const int t = threadIdx.x;
    const int role = blockIdx.x & 1;
    const int colbase = role * NHALF;

    // one-time staging: w2 half, w1, b1, b2 half
    #pragma unroll
    for (int r = 0; r < 64; ++r) {
        int i = t + r * THREADS;
        int k = i >> 9, n = i & 511;
        sW2[i] = w2[k * 1024 + colbase + n];
    }
    for (int i = t; i < 16 * 64; i += THREADS) sW1[i] = w1[i];
    if (t < 64) sB1[t] = b1[t];
    if (t < NHALF) sB2[t] = b2[colbase + t];
    __syncthreads();

    const float ALPHA = 0.17677669529663687f;   // 1/sqrt(2*MUL)
    const float INV3  = 0.5773502691896258f;    // 1/sqrt(3)

    // GEMM thread tile: 8 edges x 4 cols
    const int rg = (t >> 7) << 3;       // edge row base: 0,8,16,24
    const int cb = (t & 127) << 2;      // col base: 0..508 step 4

    const int nrole = gridDim.x >> 1;
    for (int tile = blockIdx.x >> 1; tile < EE / TE; tile += nrole) {
        const int e0 = tile * TE;

        // ---- phase 0: stage edge meta ----
        if (t < 32)       sSrc[t]      = eidx[e0 + t];
        else if (t < 64)  sDst[t - 32] = eidx[EE + e0 + (t - 32)];
        else if (t < 192) sSH[t - 64]  = esh[e0 * 4 + (t - 64)];
        {
            int k = t >> 5, e = t & 31;
            sEmbT[k * 32 + e] = emb[(e0 + e) * 16 + k];
        }
        __syncthreads();

        // ---- phase 1: contraction vectors + hidden h (duplicated pairs) ----
        {
            int e = t >> 4, u = t & 15;
            int src = sSrc[e];
            float shs = sSH[e * 4];
            if (role == 0) {
                float x = nf[src * 64 + u];
                sX[e * 64 + u]      = x;         // xs  (for y01)
                sX[e * 64 + 16 + u] = shs * x;   // a   (for y00)
            } else {
                float sh1 = sSH[e*4+1], sh2 = sSH[e*4+2], sh3 = sSH[e*4+3];
                float xv0 = nf[src*64 + 16 + u*3 + 0];
                float xv1 = nf[src*64 + 16 + u*3 + 1];
                float xv2 = nf[src*64 + 16 + u*3 + 2];
                sX[e*64 + u]      = sh1*xv0 + sh2*xv1 + sh3*xv2; // b (for y11)
                sX[e*64 + 16 + u] = shs * xv0;                   // y10 i=0
                sX[e*64 + 32 + u] = shs * xv1;                   // i=1
                sX[e*64 + 48 + u] = shs * xv2;                   // i=2
            }
        }
        #pragma unroll
        for (int r = 0; r < 4; ++r) {
            int task = t + r * THREADS;          // 2048 = 32 e * 64 hidden
            int e = task & 31, j = task >> 5;    // j warp-uniform, e lane-linear
            float acc = sB1[j];
            #pragma unroll
            for (int k = 0; k < 16; ++k) acc += sEmbT[k * 32 + e] * sW1[k * 64 + j];
            float h = acc / (1.0f + __expf(-acc));   // silu
            sHd[j * 32 + e] = pack_dup(h);
        }
        __syncthreads();

        // ---- phase 2: GEMM  W[32 x 512] = H[32 x 64] @ w2half[64 x 512] ----
        unsigned long long acc[8][2];
        #pragma unroll
        for (int i = 0; i < 8; ++i) { acc[i][0] = 0ull; acc[i][1] = 0ull; }

        #pragma unroll 8
        for (int k = 0; k < 64; ++k) {
            const unsigned long long* hr = sHd + k * 32 + rg;
            ulonglong2 a01 = *reinterpret_cast<const ulonglong2*>(hr);
            ulonglong2 a23 = *reinterpret_cast<const ulonglong2*>(hr + 2);
            ulonglong2 a45 = *reinterpret_cast<const ulonglong2*>(hr + 4);
            ulonglong2 a67 = *reinterpret_cast<const ulonglong2*>(hr + 6);
            ulonglong2 b   = *reinterpret_cast<const ulonglong2*>(sW2 + k * NHALF + cb);
            FMA2(acc[0][0], a01.x, b.x); FMA2(acc[0][1], a01.x, b.y);
            FMA2(acc[1][0], a01.y, b.x); FMA2(acc[1][1], a01.y, b.y);
            FMA2(acc[2][0], a23.x, b.x); FMA2(acc[2][1], a23.x, b.y);
            FMA2(acc[3][0], a23.y, b.x); FMA2(acc[3][1], a23.y, b.y);
            FMA2(acc[4][0], a45.x, b.x); FMA2(acc[4][1], a45.x, b.y);
            FMA2(acc[5][0], a45.y, b.x); FMA2(acc[5][1], a45.y, b.y);
            FMA2(acc[6][0], a67.x, b.x); FMA2(acc[6][1], a67.x, b.y);
            FMA2(acc[7][0], a67.y, b.x); FMA2(acc[7][1], a67.y, b.y);
        }
        // epilogue: +bias, store; upper 256 cols stored XOR-16 swizzled
        {
            float4 bias = *reinterpret_cast<const float4*>(sB2 + cb);
            int scb = (cb < 256) ? cb : (cb ^ 16);
            #pragma unroll
            for (int r = 0; r < 8; ++r) {
                float2 f0 = unpack2(acc[r][0]);
                float2 f1 = unpack2(acc[r][1]);
                float4 v = make_float4(f0.x + bias.x, f0.y + bias.y,
                                       f1.x + bias.z, f1.y + bias.w);
                *reinterpret_cast<float4*>(sW + (rg + r) * NHALF + scb) = v;
            }
        }
        __syncthreads();

        // ---- phase 3: contractions + atomic scatter ----
        // cols >= 256 are stored with u -> u^1 permutation (XOR-16 swizzle)
        if (role == 0) {
            #pragma unroll
            for (int r = 0; r < 2; ++r) {
                int task = t + r * THREADS;       // 1024 = 32 e * 32 outputs
                int e = task >> 5, o = task & 31;
                int v = o & 15, sel = o >> 4;     // sel0: y00 (a), sel1: y01 (xs, swizzled)
                const float* w = sW + e * NHALF + (sel ? 256 + v : v);
                const float* x = sX + e * 64 + (sel ? 0 : 16);
                int xm = sel;                     // u^1 for swizzled half
                float y = 0.0f;
                #pragma unroll
                for (int u = 0; u < 16; ++u) y += x[u ^ xm] * w[u * 16];
                int dst = sDst[e];
                if (sel == 0) {
                    atomicAdd(&g_agg[dst * 64 + v], ALPHA * y);
                } else {
                    float ay = ALPHA * y;
                    atomicAdd(&g_agg[dst*64 + 16 + v*3 + 0], ay * sSH[e*4+1]);
                    atomicAdd(&g_agg[dst*64 + 16 + v*3 + 1], ay * sSH[e*4+2]);
                    atomicAdd(&g_agg[dst*64 + 16 + v*3 + 2], ay * sSH[e*4+3]);
                }
            }
        } else {
            #pragma unroll
            for (int r = 0; r < 4; ++r) {
                int task = t + r * THREADS;       // 2048 = 32 e * 64 outputs
                int e = task >> 6, o = task & 63;
                int dst = sDst[e];
                if (o < 16) {                     // y11 (b, swizzled cols): phys u, x[u^1]
                    int v = o;
                    const float* x = sX + e * 64;
                    const float* w = sW + e * NHALF + 256 + v;
                    float y = 0.0f;
                    #pragma unroll
                    for (int u = 0; u < 16; ++u) y += x[u ^ 1] * w[u * 16];
                    atomicAdd(&g_agg[dst * 64 + v], ALPHA * INV3 * y);
                } else {                          // y10_i: phase-shifted u for bank parity
                    int oo = o - 16;
                    int i = oo >> 4, v = oo & 15;
                    const float* x = sX + e * 64 + 16 + i * 16;
                    const float* w = sW + e * NHALF + v;
                    float y = 0.0f;
                    #pragma unroll
                    for (int u = 0; u < 16; ++u) {
                        int uu = (u + 1) & 15;
                        y += x[uu] * w[uu * 16];
                    }
                    atomicAdd(&g_agg[dst * 64 + 16 + v * 3 + i], ALPHA * y);
                }
            }
        }
        __syncthreads();
    }
}

__global__ __launch_bounds__(256)
void node_kernel(const float* __restrict__ nf,
                 const float* __restrict__ lw0,
                 const float* __restrict__ lw1,
                 float* __restrict__ out)
{
    __shared__ float sw0[256], sw1[256];
    int t = threadIdx.x;
    sw0[t] = lw0[t];
    sw1[t] = lw1[t];
    __syncthreads();

    int node = blockIdx.x * 16 + (t >> 4);
    int v = t & 15;
    const float* a = g_agg + node * 64;

    float ts = 0.0f, t0 = 0.0f, t1 = 0.0f, t2 = 0.0f;
    #pragma unroll
    for (int u = 0; u < 16; ++u) {
        float c0 = sw0[u * 16 + v];
        float c1 = sw1[u * 16 + v];
        ts += a[u] * c0;
        t0 += a[16 + u * 3 + 0] * c1;
        t1 += a[16 + u * 3 + 1] * c1;
        t2 += a[16 + u * 3 + 2] * c1;
    }
    const float S = 0.25f, EPS = 1e-8f;
    ts *= S; t0 *= S; t1 *= S; t2 *= S;

    float ns = fabsf(ts);
    float gs = ns / ((ns + EPS) * (1.0f + __expf(-ns)));
    float nv = sqrtf(t0 * t0 + t1 * t1 + t2 * t2);
    float gv = nv / ((nv + EPS) * (1.0f + __expf(-nv)));

    int base = node * 64;
    out[base + v] = nf[base + v] + ts * gs;
    out[base + 16 + v * 3 + 0] = nf[base + 16 + v * 3 + 0] + t0 * gv;
    out[base + 16 + v * 3 + 1] = nf[base + 16 + v * 3 + 1] + t1 * gv;
    out[base + 16 + v * 3 + 2] = nf[base + 16 + v * 3 + 2] + t2 * gv;
}

extern "C" void kernel_launch(void* const* d_in, const int* in_sizes, int n_in,
                              void* d_out, int out_size)
{
    const float* nf   = (const float*)d_in[0];
    const float* esh  = (const float*)d_in[1];
    const float* emb  = (const float*)d_in[2];
    const float* w1   = (const float*)d_in[3];
    const float* b1   = (const float*)d_in[4];
    const float* w2   = (const float*)d_in[5];
    const float* b2   = (const float*)d_in[6];
    const float* lw0  = (const float*)d_in[7];
    const float* lw1  = (const float*)d_in[8];
    const int*   eidx = (const int*)d_in[9];
    float* out = (float*)d_out;

    cudaFuncSetAttribute(edge_kernel, cudaFuncAttributeMaxDynamicSharedMemorySize, SMEM_BYTES);

    zero_kernel<<<625, 1024>>>();
    edge_kernel<<<148, THREADS, SMEM_BYTES>>>(nf, esh, emb, w1, b1, w2, b2, eidx);
    node_kernel<<<625, 256>>>(nf, lw0, lw1, out);
}

// round 7
// speedup vs baseline: 1.4663x; 1.4663x over previous
#include <cuda_runtime.h>
#include <cuda_bf16.h>
#include <cstdint>
#include <math.h>

#define NN 10000
#define EE 160000
#define TE 128
#define THREADS 512

// ---- shared memory byte offsets ----
#define SM_BHI 0         // 256 rows x 64 bf16 (128B rows), SW128
#define SM_BLO 32768
#define SM_AHI 65536     // 128 rows x 64 bf16 (128B rows), SW128
#define SM_ALO 81920
#define SM_C   98304     // 128 x 132 fp32 (padded rows)
#define SM_XT  165888    // 48 x 128 fp32
#define SM_EMB 190464    // 128 x 16 fp32
#define SM_W1  198656    // 16 x 64 fp32
#define SM_B1  202752    // 64 fp32
#define SM_B2P 203008    // 256 fp32 (permuted quadrant bias)
#define SM_SH  204032    // 128 x 4 fp32
#define SM_SRC 206080    // 128 int
#define SM_DST 206592    // 128 int
#define SMEM_TOTAL 207104

#define SW128(x) ((x) ^ (((x) >> 3) & 0x70))
#define CPAD 132

__device__ float g_agg[NN * 64];

static __device__ __forceinline__ uint32_t smem_u32(const void* p) {
    uint32_t a;
    asm("{ .reg .u64 t; cvta.to.shared.u64 t, %1; cvt.u32.u64 %0, t; }" : "=r"(a) : "l"(p));
    return a;
}

#define LDSM4(r0, r1, r2, r3, addr) \
    asm volatile("ldmatrix.sync.aligned.m8n8.x4.shared.b16 {%0,%1,%2,%3}, [%4];" \
                 : "=r"(r0), "=r"(r1), "=r"(r2), "=r"(r3) : "r"(addr))

#define MMA16816(d, a, b0, b1) \
    asm volatile("mma.sync.aligned.m16n8k16.row.col.f32.bf16.bf16.f32 " \
                 "{%0,%1,%2,%3}, {%4,%5,%6,%7}, {%8,%9}, {%0,%1,%2,%3};" \
                 : "+f"((d)[0]), "+f"((d)[1]), "+f"((d)[2]), "+f"((d)[3]) \
                 : "r"((a)[0]), "r"((a)[1]), "r"((a)[2]), "r"((a)[3]), "r"(b0), "r"(b1))

__global__ void zero_kernel() {
    g_agg[blockIdx.x * 1024 + threadIdx.x] = 0.0f;
}

__global__ __launch_bounds__(THREADS, 1)
void edge_kernel(const float* __restrict__ nf,
                 const float* __restrict__ esh,
                 const float* __restrict__ emb,
                 const float* __restrict__ w1,
                 const float* __restrict__ b1,
                 const float* __restrict__ w2,
                 const float* __restrict__ b2,
                 const int*   __restrict__ eidx)
{
    extern __shared__ __align__(1024) char sm[];
    const uint32_t sbase = smem_u32(sm);

    const int t = threadIdx.x;
    const int wid = t >> 5, lid = t & 31;
    const int qd = blockIdx.x & 3;           // quadrant role 0..3

    float* sC   = (float*)(sm + SM_C);
    float* sXT  = (float*)(sm + SM_XT);
    float* sEmb = (float*)(sm + SM_EMB);
    float* sW1  = (float*)(sm + SM_W1);
    float* sB1  = (float*)(sm + SM_B1);
    float* sB2P = (float*)(sm + SM_B2P);
    float* sSH  = (float*)(sm + SM_SH);
    int*   sSrc = (int*)(sm + SM_SRC);
    int*   sDst = (int*)(sm + SM_DST);

    // ---- one-time staging: w2 quadrant (bf16 hi/lo, transposed+permuted), b2, w1, b1 ----
    for (int idx = t; idx < 64 * 256; idx += THREADS) {
        int k = idx >> 8, j = idx & 255;             // j = u*16+v within quadrant
        float w = w2[k * 1024 + qd * 256 + j];
        int p = ((j & 15) << 4) | (j >> 4);          // p = v*16+u
        __nv_bfloat16 hi = __float2bfloat16(w);
        __nv_bfloat16 lo = __float2bfloat16(w - __bfloat162float(hi));
        uint32_t off = SW128((uint32_t)(p * 128 + k * 2));
        *(__nv_bfloat16*)(sm + SM_BHI + off) = hi;
        *(__nv_bfloat16*)(sm + SM_BLO + off) = lo;
    }
    if (t < 256) {
        int j = t;
        int p = ((j & 15) << 4) | (j >> 4);
        sB2P[p] = b2[qd * 256 + j];
    }
    for (int i = t; i < 1024; i += THREADS) sW1[i] = w1[i];
    if (t < 64) sB1[t] = b1[t];
    __syncthreads();

    const float ALPHA = 0.17677669529663687f;   // 1/sqrt(2*16)
    const float INV3  = 0.5773502691896258f;    // 1/sqrt(3)

    // MMA warp tiling: warp tile 32e x 32p per chunk
    const int wy = wid & 3;                    // e block
    const int wx = wid >> 2;                   // p block within chunk
    // ldmatrix lane params
    const int mi = lid >> 3, r = lid & 7;
    const int a_row_base = wy * 32 + ((mi & 1) << 3) + r;
    const uint32_t a_kb = (uint32_t)((mi >> 1) << 4);
    const int b_row_off = ((mi >> 1) << 3) + r;
    const uint32_t b_kb = (uint32_t)((mi & 1) << 4);
    const uint32_t lmask = (uint32_t)(r << 4);
    // C-store lane params
    const int gid = lid >> 2, tid4 = lid & 3;

    for (int tile = blockIdx.x >> 2; tile < EE / TE; tile += 37) {
        const int e0 = tile * TE;

        // ---- phase 0: stage edge meta ----
        if (t < 128)      sSrc[t] = eidx[e0 + t];
        else if (t < 256) sDst[t - 128] = eidx[EE + e0 + (t - 128)];
        sSH[t] = esh[e0 * 4 + t];
        #pragma unroll
        for (int rr = 0; rr < 4; ++rr) sEmb[t + rr * THREADS] = emb[e0 * 16 + t + rr * THREADS];
        __syncthreads();

        // ---- phase 1a: stage x vectors (raw) ----
        {
            int e = t >> 2, q4 = t & 3;
            int src = sSrc[e];
            if (qd < 2) {                       // xs: rows 0..15
                float4 x4 = *(const float4*)(nf + src * 64 + q4 * 4);
                int r0 = q4 * 4;
                sXT[(r0 + 0) * 128 + e] = x4.x;
                sXT[(r0 + 1) * 128 + e] = x4.y;
                sXT[(r0 + 2) * 128 + e] = x4.z;
                sXT[(r0 + 3) * 128 + e] = x4.w;
            } else {                            // xv: rows u*3+i (48)
                #pragma unroll
                for (int b = 0; b < 3; ++b) {
                    int m0 = q4 * 12 + b * 4;
                    float4 x4 = *(const float4*)(nf + src * 64 + 16 + m0);
                    sXT[(m0 + 0) * 128 + e] = x4.x;
                    sXT[(m0 + 1) * 128 + e] = x4.y;
                    sXT[(m0 + 2) * 128 + e] = x4.z;
                    sXT[(m0 + 3) * 128 + e] = x4.w;
                }
            }
        }

        // ---- phase 1b: H = silu(emb@w1+b1) -> bf16 hi/lo A tiles (SW128) ----
        #pragma unroll
        for (int rr = 0; rr < 8; ++rr) {
            int task = t + rr * THREADS;            // 4096 = 128e x 32 j-pairs
            int e = task >> 5, jp = task & 31;
            const float* er = sEmb + e * 16;
            float a0 = sB1[2 * jp], a1 = sB1[2 * jp + 1];
            #pragma unroll
            for (int k = 0; k < 16; ++k) {
                float ev = er[k];
                float2 wv = *(const float2*)(sW1 + k * 64 + 2 * jp);
                a0 += ev * wv.x;
                a1 += ev * wv.y;
            }
            float h0 = a0 / (1.0f + __expf(-a0));
            float h1 = a1 / (1.0f + __expf(-a1));
            __nv_bfloat16 h0h = __float2bfloat16(h0);
            __nv_bfloat16 h1h = __float2bfloat16(h1);
            __nv_bfloat16 h0l = __float2bfloat16(h0 - __bfloat162float(h0h));
            __nv_bfloat16 h1l = __float2bfloat16(h1 - __bfloat162float(h1h));
            uint32_t hi2 = (uint32_t)__bfloat16_as_ushort(h0h) |
                           ((uint32_t)__bfloat16_as_ushort(h1h) << 16);
            uint32_t lo2 = (uint32_t)__bfloat16_as_ushort(h0l) |
                           ((uint32_t)__bfloat16_as_ushort(h1l) << 16);
            uint32_t off = SW128((uint32_t)(e * 128 + jp * 4));
            *(uint32_t*)(sm + SM_AHI + off) = hi2;
            *(uint32_t*)(sm + SM_ALO + off) = lo2;
        }
        __syncthreads();

        // ---- per chunk: MMA -> C smem -> contraction -> scatter ----
        #pragma unroll 1
        for (int c = 0; c < 2; ++c) {
            const int cbase = c << 7;

            float acc[2][4][4];
            #pragma unroll
            for (int m = 0; m < 2; ++m)
                #pragma unroll
                for (int nt = 0; nt < 4; ++nt)
                    #pragma unroll
                    for (int z = 0; z < 4; ++z) acc[m][nt][z] = 0.0f;

            #pragma unroll
            for (int ks = 0; ks < 4; ++ks) {
                const uint32_t kx = (uint32_t)(ks * 32);
                uint32_t ah[2][4], al[2][4], bh[2][4], bl[2][4];
                #pragma unroll
                for (int m = 0; m < 2; ++m) {
                    uint32_t row = (uint32_t)(a_row_base + m * 16);
                    uint32_t ad = sbase + SM_AHI + row * 128 + ((kx + a_kb) ^ lmask);
                    LDSM4(ah[m][0], ah[m][1], ah[m][2], ah[m][3], ad);
                    LDSM4(al[m][0], al[m][1], al[m][2], al[m][3], ad + (SM_ALO - SM_AHI));
                }
                #pragma unroll
                for (int pr = 0; pr < 2; ++pr) {
                    uint32_t p = (uint32_t)(cbase + wx * 32 + pr * 16 + b_row_off);
                    uint32_t bd = sbase + SM_BHI + p * 128 + ((kx + b_kb) ^ lmask);
                    LDSM4(bh[pr][0], bh[pr][1], bh[pr][2], bh[pr][3], bd);
                    LDSM4(bl[pr][0], bl[pr][1], bl[pr][2], bl[pr][3], bd + (SM_BLO - SM_BHI));
                }
                #pragma unroll
                for (int m = 0; m < 2; ++m)
                    #pragma unroll
                    for (int pr = 0; pr < 2; ++pr)
                        #pragma unroll
                        for (int sb = 0; sb < 2; ++sb) {
                            float* d = acc[m][pr * 2 + sb];
                            MMA16816(d, ah[m], bh[pr][sb * 2], bh[pr][sb * 2 + 1]);
                            MMA16816(d, ah[m], bl[pr][sb * 2], bl[pr][sb * 2 + 1]);
                            MMA16816(d, al[m], bh[pr][sb * 2], bh[pr][sb * 2 + 1]);
                        }
            }

            // store C + bias to smem (padded rows)
            #pragma unroll
            for (int m = 0; m < 2; ++m)
                #pragma unroll
                for (int nt = 0; nt < 4; ++nt) {
                    int colp = wx * 32 + nt * 8 + tid4 * 2;
                    float b0 = sB2P[cbase + colp], b1v = sB2P[cbase + colp + 1];
                    int row0 = wy * 32 + m * 16 + gid;
                    float2 v01 = make_float2(acc[m][nt][0] + b0, acc[m][nt][1] + b1v);
                    float2 v23 = make_float2(acc[m][nt][2] + b0, acc[m][nt][3] + b1v);
                    *(float2*)&sC[row0 * CPAD + colp] = v01;
                    *(float2*)&sC[(row0 + 8) * CPAD + colp] = v23;
                }
            __syncthreads();

            // contraction + scatter (8 v per chunk; thread does 2)
            {
                int e = t & 127;
                int vg = t >> 7;
                int dst = sDst[e];
                float sh0 = sSH[e * 4 + 0], sh1 = sSH[e * 4 + 1];
                float sh2 = sSH[e * 4 + 2], sh3 = sSH[e * 4 + 3];
                #pragma unroll
                for (int jj = 0; jj < 2; ++jj) {
                    int vl = vg * 2 + jj;
                    int v = c * 8 + vl;
                    const float* crow = sC + e * CPAD + vl * 16;
                    float4 c0 = *(const float4*)(crow);
                    float4 c1 = *(const float4*)(crow + 4);
                    float4 c2 = *(const float4*)(crow + 8);
                    float4 c3 = *(const float4*)(crow + 12);
                    float cr[16] = {c0.x, c0.y, c0.z, c0.w, c1.x, c1.y, c1.z, c1.w,
                                    c2.x, c2.y, c2.z, c2.w, c3.x, c3.y, c3.z, c3.w};
                    if (qd < 2) {
                        float y = 0.0f;
                        #pragma unroll
                        for (int u = 0; u < 16; ++u) y += sXT[u * 128 + e] * cr[u];
                        if (qd == 0) {
                            atomicAdd(&g_agg[dst * 64 + v], ALPHA * sh0 * y);
                        } else {
                            float ay = ALPHA * y;
                            atomicAdd(&g_agg[dst * 64 + 16 + v * 3 + 0], ay * sh1);
                            atomicAdd(&g_agg[dst * 64 + 16 + v * 3 + 1], ay * sh2);
                            atomicAdd(&g_agg[dst * 64 + 16 + v * 3 + 2], ay * sh3);
                        }
                    } else {
                        float z0 = 0.0f, z1 = 0.0f, z2 = 0.0f;
                        #pragma unroll
                        for (int u = 0; u < 16; ++u) {
                            float cv = cr[u];
                            z0 += sXT[(u * 3 + 0) * 128 + e] * cv;
                            z1 += sXT[(u * 3 + 1) * 128 + e] * cv;
                            z2 += sXT[(u * 3 + 2) * 128 + e] * cv;
                        }
                        if (qd == 2) {
                            float s = ALPHA * sh0;
                            atomicAdd(&g_agg[dst * 64 + 16 + v * 3 + 0], s * z0);
                            atomicAdd(&g_agg[dst * 64 + 16 + v * 3 + 1], s * z1);
                            atomicAdd(&g_agg[dst * 64 + 16 + v * 3 + 2], s * z2);
                        } else {
                            float y = sh1 * z0 + sh2 * z1 + sh3 * z2;
                            atomicAdd(&g_agg[dst * 64 + v], ALPHA * INV3 * y);
                        }
                    }
                }
            }
            __syncthreads();
        }
    }
}

__global__ __launch_bounds__(256)
void node_kernel(const float* __restrict__ nf,
                 const float* __restrict__ lw0,
                 const float* __restrict__ lw1,
                 float* __restrict__ out)
{
    __shared__ float sw0[256], sw1[256];
    int t = threadIdx.x;
    sw0[t] = lw0[t];
    sw1[t] = lw1[t];
    __syncthreads();

    int node = blockIdx.x * 16 + (t >> 4);
    int v = t & 15;
    const float* a = g_agg + node * 64;

    float ts = 0.0f, t0 = 0.0f, t1 = 0.0f, t2 = 0.0f;
    #pragma unroll
    for (int u = 0; u < 16; ++u) {
        float c0 = sw0[u * 16 + v];
        float c1 = sw1[u * 16 + v];
        ts += a[u] * c0;
        t0 += a[16 + u * 3 + 0] * c1;
        t1 += a[16 + u * 3 + 1] * c1;
        t2 += a[16 + u * 3 + 2] * c1;
    }
    const float S = 0.25f, EPS = 1e-8f;
    ts *= S; t0 *= S; t1 *= S; t2 *= S;

    float ns = fabsf(ts);
    float gs = ns / ((ns + EPS) * (1.0f + __expf(-ns)));
    float nv = sqrtf(t0 * t0 + t1 * t1 + t2 * t2);
    float gv = nv / ((nv + EPS) * (1.0f + __expf(-nv)));

    int base = node * 64;
    out[base + v] = nf[base + v] + ts * gs;
    out[base + 16 + v * 3 + 0] = nf[base + 16 + v * 3 + 0] + t0 * gv;
    out[base + 16 + v * 3 + 1] = nf[base + 16 + v * 3 + 1] + t1 * gv;
    out[base + 16 + v * 3 + 2] = nf[base + 16 + v * 3 + 2] + t2 * gv;
}

extern "C" void kernel_launch(void* const* d_in, const int* in_sizes, int n_in,
                              void* d_out, int out_size)
{
    const float* nf   = (const float*)d_in[0];
    const float* esh  = (const float*)d_in[1];
    const float* emb  = (const float*)d_in[2];
    const float* w1   = (const float*)d_in[3];
    const float* b1   = (const float*)d_in[4];
    const float* w2   = (const float*)d_in[5];
    const float* b2   = (const float*)d_in[6];
    const float* lw0  = (const float*)d_in[7];
    const float* lw1  = (const float*)d_in[8];
    const int*   eidx = (const int*)d_in[9];
    float* out = (float*)d_out;

    cudaFuncSetAttribute(edge_kernel, cudaFuncAttributeMaxDynamicSharedMemorySize, SMEM_TOTAL);

    zero_kernel<<<625, 1024>>>();
    edge_kernel<<<148, THREADS, SMEM_TOTAL>>>(nf, esh, emb, w1, b1, w2, b2, eidx);
    node_kernel<<<625, 256>>>(nf, lw0, lw1, out);
}

// round 10
// speedup vs baseline: 1.8161x; 1.2386x over previous
#include <cuda_runtime.h>
#include <cuda_bf16.h>
#include <cstdint>
#include <math.h>

#define NN 10000
#define EE 160000
#define TE 128
#define THREADS 512

// ---- shared memory byte offsets ----
#define SM_BHI 0         // 256 rows x 64 bf16 (128B rows), SW128
#define SM_BLO 32768
#define SM_AHI 65536     // 128 rows x 64 bf16 (128B rows), SW128
#define SM_ALO 81920
#define SM_C   98304     // 128 x 132 fp32 (padded rows) = 67584B
#define SM_XT  165888    // 64 x 128 fp32 = 32768B
#define SM_EMB 198656    // 128 x 16 fp32
#define SM_W1  206848    // 16 x 64 fp32
#define SM_B1  210944    // 64 fp32
#define SM_B2P 211200    // 256 fp32 (permuted quadrant bias)
#define SM_SH  212224    // 128 x 4 fp32
#define SM_SRC 214272    // 128 int
#define SM_DST 214784    // 128 int
#define SMEM_TOTAL 215296

#define SW128(x) ((x) ^ (((x) >> 3) & 0x70))
#define CPAD 132

__device__ float g_agg[NN * 64];

static __device__ __forceinline__ uint32_t smem_u32(const void* p) {
    uint32_t a;
    asm("{ .reg .u64 t; cvta.to.shared.u64 t, %1; cvt.u32.u64 %0, t; }" : "=r"(a) : "l"(p));
    return a;
}

#define LDSM4(r0, r1, r2, r3, addr) \
    asm volatile("ldmatrix.sync.aligned.m8n8.x4.shared.b16 {%0,%1,%2,%3}, [%4];" \
                 : "=r"(r0), "=r"(r1), "=r"(r2), "=r"(r3) : "r"(addr))

#define MMA16816(d, a, b0, b1) \
    asm volatile("mma.sync.aligned.m16n8k16.row.col.f32.bf16.bf16.f32 " \
                 "{%0,%1,%2,%3}, {%4,%5,%6,%7}, {%8,%9}, {%0,%1,%2,%3};" \
                 : "+f"((d)[0]), "+f"((d)[1]), "+f"((d)[2]), "+f"((d)[3]) \
                 : "r"((a)[0]), "r"((a)[1]), "r"((a)[2]), "r"((a)[3]), "r"(b0), "r"(b1))

__global__ void zero_kernel() {
    g_agg[blockIdx.x * 1024 + threadIdx.x] = 0.0f;
}

__global__ __launch_bounds__(THREADS, 1)
void edge_kernel(const float* __restrict__ nf,
                 const float* __restrict__ esh,
                 const float* __restrict__ emb,
                 const float* __restrict__ w1,
                 const float* __restrict__ b1,
                 const float* __restrict__ w2,
                 const float* __restrict__ b2,
                 const int*   __restrict__ eidx)
{
    extern __shared__ __align__(1024) char sm[];
    const uint32_t sbase = smem_u32(sm);

    const int t = threadIdx.x;
    const int wid = t >> 5, lid = t & 31;
    const int qd = blockIdx.x & 3;           // v-quarter role 0..3

    float* sC   = (float*)(sm + SM_C);
    float* sXT  = (float*)(sm + SM_XT);
    float* sEmb = (float*)(sm + SM_EMB);
    float* sW1  = (float*)(sm + SM_W1);
    float* sB1  = (float*)(sm + SM_B1);
    float* sB2P = (float*)(sm + SM_B2P);
    float* sSH  = (float*)(sm + SM_SH);
    int*   sSrc = (int*)(sm + SM_SRC);
    int*   sDst = (int*)(sm + SM_DST);

    // ---- one-time staging ----
    // B physical row p = b*64 + vl*16 + u  ->  w2 col n = b*256 + u*16 + (qd*4+vl)
    for (int idx = t; idx < 64 * 256; idx += THREADS) {
        int k = idx >> 8, p = idx & 255;
        int b = p >> 6, vl = (p >> 4) & 3, u = p & 15;
        int n = b * 256 + u * 16 + qd * 4 + vl;
        float w = w2[k * 1024 + n];
        __nv_bfloat16 hi = __float2bfloat16(w);
        __nv_bfloat16 lo = __float2bfloat16(w - __bfloat162float(hi));
        uint32_t off = SW128((uint32_t)(p * 128 + k * 2));
        *(__nv_bfloat16*)(sm + SM_BHI + off) = hi;
        *(__nv_bfloat16*)(sm + SM_BLO + off) = lo;
    }
    if (t < 256) {
        int p = t;
        int b = p >> 6, vl = (p >> 4) & 3, u = p & 15;
        sB2P[p] = b2[b * 256 + u * 16 + qd * 4 + vl];
    }
    for (int i = t; i < 1024; i += THREADS) sW1[i] = w1[i];
    if (t < 64) sB1[t] = b1[t];
    __syncthreads();

    const float ALPHA = 0.17677669529663687f;   // 1/sqrt(2*16)
    const float INV3  = 0.5773502691896258f;    // 1/sqrt(3)

    // MMA warp tiling: warp tile 32e x 32p per chunk
    const int wy = wid & 3;                    // e block
    const int wx = wid >> 2;                   // p block within chunk
    const int mi = lid >> 3, r = lid & 7;
    const int a_row_base = wy * 32 + ((mi & 1) << 3) + r;
    const uint32_t a_kb = (uint32_t)((mi >> 1) << 4);
    const int b_row_off = ((mi >> 1) << 3) + r;
    const uint32_t b_kb = (uint32_t)((mi & 1) << 4);
    const uint32_t lmask = (uint32_t)(r << 4);
    const int gid = lid >> 2, tid4 = lid & 3;

    // contraction mapping: e = t&127 (warp lanes consecutive e), vl = t>>7
    const int ce = t & 127;
    const int cvl = t >> 7;

    for (int tile = blockIdx.x >> 2; tile < EE / TE; tile += 37) {
        const int e0 = tile * TE;

        // ---- phase 0: stage edge meta ----
        if (t < 128)      sSrc[t] = eidx[e0 + t];
        else if (t < 256) sDst[t - 128] = eidx[EE + e0 + (t - 128)];
        sSH[t] = esh[e0 * 4 + t];
        #pragma unroll
        for (int rr = 0; rr < 4; ++rr) sEmb[t + rr * THREADS] = emb[e0 * 16 + t + rr * THREADS];
        __syncthreads();

        // ---- phase 1a: stage x vectors (all 64 components) ----
        // row<16: xs[u]; row>=16: xv[u][i] at row 16 + i*16 + u
        {
            int e = t >> 2, q4 = t & 3;
            int src = sSrc[e];
            #pragma unroll
            for (int b = 0; b < 4; ++b) {
                float4 x4 = *(const float4*)(nf + src * 64 + q4 * 16 + b * 4);
                float vals[4] = {x4.x, x4.y, x4.z, x4.w};
                #pragma unroll
                for (int j = 0; j < 4; ++j) {
                    int m = q4 * 16 + b * 4 + j;           // 0..63
                    int row;
                    if (m < 16) row = m;
                    else { int mm = m - 16; row = 16 + (mm % 3) * 16 + (mm / 3); }
                    sXT[row * 128 + e] = vals[j];
                }
            }
        }

        // ---- phase 1b: H = silu(emb@w1+b1) -> bf16 hi/lo A tiles (SW128) ----
        #pragma unroll
        for (int rr = 0; rr < 8; ++rr) {
            int task = t + rr * THREADS;            // 4096 = 128e x 32 j-pairs
            int e = task >> 5, jp = task & 31;
            const float* er = sEmb + e * 16;
            float a0 = sB1[2 * jp], a1 = sB1[2 * jp + 1];
            #pragma unroll
            for (int k = 0; k < 16; ++k) {
                float ev = er[k];
                float2 wv = *(const float2*)(sW1 + k * 64 + 2 * jp);
                a0 += ev * wv.x;
                a1 += ev * wv.y;
            }
            float h0 = a0 / (1.0f + __expf(-a0));
            float h1 = a1 / (1.0f + __expf(-a1));
            __nv_bfloat16 h0h = __float2bfloat16(h0);
            __nv_bfloat16 h1h = __float2bfloat16(h1);
            __nv_bfloat16 h0l = __float2bfloat16(h0 - __bfloat162float(h0h));
            __nv_bfloat16 h1l = __float2bfloat16(h1 - __bfloat162float(h1h));
            uint32_t hi2 = (uint32_t)__bfloat16_as_ushort(h0h) |
                           ((uint32_t)__bfloat16_as_ushort(h1h) << 16);
            uint32_t lo2 = (uint32_t)__bfloat16_as_ushort(h0l) |
                           ((uint32_t)__bfloat16_as_ushort(h1l) << 16);
            uint32_t off = SW128((uint32_t)(e * 128 + jp * 4));
            *(uint32_t*)(sm + SM_AHI + off) = hi2;
            *(uint32_t*)(sm + SM_ALO + off) = lo2;
        }
        __syncthreads();

        // ---- per chunk: MMA -> C smem -> partial contraction; scatter after chunk1 ----
        float y00 = 0.0f, y01 = 0.0f;
        float z10_0 = 0.0f, z10_1 = 0.0f, z10_2 = 0.0f;
        float z11_0 = 0.0f, z11_1 = 0.0f, z11_2 = 0.0f;

        #pragma unroll 1
        for (int c = 0; c < 2; ++c) {
            const int cbase = c << 7;

            float acc[2][4][4];
            #pragma unroll
            for (int m = 0; m < 2; ++m)
                #pragma unroll
                for (int nt = 0; nt < 4; ++nt)
                    #pragma unroll
                    for (int z = 0; z < 4; ++z) acc[m][nt][z] = 0.0f;

            #pragma unroll
            for (int ks = 0; ks < 4; ++ks) {
                const uint32_t kx = (uint32_t)(ks * 32);
                uint32_t ah[2][4], al[2][4], bh[2][4], bl[2][4];
                #pragma unroll
                for (int m = 0; m < 2; ++m) {
                    uint32_t row = (uint32_t)(a_row_base + m * 16);
                    uint32_t ad = sbase + SM_AHI + row * 128 + ((kx + a_kb) ^ lmask);
                    LDSM4(ah[m][0], ah[m][1], ah[m][2], ah[m][3], ad);
                    LDSM4(al[m][0], al[m][1], al[m][2], al[m][3], ad + (SM_ALO - SM_AHI));
                }
                #pragma unroll
                for (int pr = 0; pr < 2; ++pr) {
                    uint32_t p = (uint32_t)(cbase + wx * 32 + pr * 16 + b_row_off);
                    uint32_t bd = sbase + SM_BHI + p * 128 + ((kx + b_kb) ^ lmask);
                    LDSM4(bh[pr][0], bh[pr][1], bh[pr][2], bh[pr][3], bd);
                    LDSM4(bl[pr][0], bl[pr][1], bl[pr][2], bl[pr][3], bd + (SM_BLO - SM_BHI));
                }
                #pragma unroll
                for (int m = 0; m < 2; ++m)
                    #pragma unroll
                    for (int pr = 0; pr < 2; ++pr)
                        #pragma unroll
                        for (int sb = 0; sb < 2; ++sb) {
                            float* d = acc[m][pr * 2 + sb];
                            MMA16816(d, ah[m], bh[pr][sb * 2], bh[pr][sb * 2 + 1]);
                            MMA16816(d, ah[m], bl[pr][sb * 2], bl[pr][sb * 2 + 1]);
                            MMA16816(d, al[m], bh[pr][sb * 2], bh[pr][sb * 2 + 1]);
                        }
            }

            // store C + bias to smem (padded rows)
            #pragma unroll
            for (int m = 0; m < 2; ++m)
                #pragma unroll
                for (int nt = 0; nt < 4; ++nt) {
                    int colp = wx * 32 + nt * 8 + tid4 * 2;
                    float b0 = sB2P[cbase + colp], b1v = sB2P[cbase + colp + 1];
                    int row0 = wy * 32 + m * 16 + gid;
                    float2 v01 = make_float2(acc[m][nt][0] + b0, acc[m][nt][1] + b1v);
                    float2 v23 = make_float2(acc[m][nt][2] + b0, acc[m][nt][3] + b1v);
                    *(float2*)&sC[row0 * CPAD + colp] = v01;
                    *(float2*)&sC[(row0 + 8) * CPAD + colp] = v23;
                }
            __syncthreads();

            // partial contraction: chunk0 -> y00 (b0), y01 (b1); chunk1 -> z10 (b2), z11 (b3)
            {
                const float* cA = sC + ce * CPAD + cvl * 16;        // b = 2c
                const float* cB = cA + 64;                           // b = 2c+1
                if (c == 0) {
                    #pragma unroll
                    for (int u = 0; u < 16; ++u) {
                        float xs = sXT[u * 128 + ce];
                        y00 += xs * cA[u];
                        y01 += xs * cB[u];
                    }
                } else {
                    #pragma unroll
                    for (int u = 0; u < 16; ++u) {
                        float w10 = cA[u], w11 = cB[u];
                        float x0 = sXT[(16 + 0 * 16 + u) * 128 + ce];
                        float x1 = sXT[(16 + 1 * 16 + u) * 128 + ce];
                        float x2 = sXT[(16 + 2 * 16 + u) * 128 + ce];
                        z10_0 += x0 * w10;  z11_0 += x0 * w11;
                        z10_1 += x1 * w10;  z11_1 += x1 * w11;
                        z10_2 += x2 * w10;  z11_2 += x2 * w11;
                    }
                }
            }
            __syncthreads();
        }

        // ---- combined scatter: 4 atomics per (e, v) ----
        {
            int dst = sDst[ce];
            float sh0 = sSH[ce * 4 + 0], sh1 = sSH[ce * 4 + 1];
            float sh2 = sSH[ce * 4 + 2], sh3 = sSH[ce * 4 + 3];
            int v = qd * 4 + cvl;
            float msg_s = ALPHA * (sh0 * y00 + INV3 * (sh1 * z11_0 + sh2 * z11_1 + sh3 * z11_2));
            atomicAdd(&g_agg[dst * 64 + v], msg_s);
            atomicAdd(&g_agg[dst * 64 + 16 + v * 3 + 0], ALPHA * (y01 * sh1 + sh0 * z10_0));
            atomicAdd(&g_agg[dst * 64 + 16 + v * 3 + 1], ALPHA * (y01 * sh2 + sh0 * z10_1));
            atomicAdd(&g_agg[dst * 64 + 16 + v * 3 + 2], ALPHA * (y01 * sh3 + sh0 * z10_2));
        }
        __syncthreads();
    }
}

__global__ __launch_bounds__(256)
void node_kernel(const float* __restrict__ nf,
                 const float* __restrict__ lw0,
                 const float* __restrict__ lw1,
                 float* __restrict__ out)
{
    __shared__ float sw0[256], sw1[256];
    int t = threadIdx.x;
    sw0[t] = lw0[t];
    sw1[t] = lw1[t];
    __syncthreads();

    int node = blockIdx.x * 16 + (t >> 4);
    int v = t & 15;
    const float* a = g_agg + node * 64;

    float ts = 0.0f, t0 = 0.0f, t1 = 0.0f, t2 = 0.0f;
    #pragma unroll
    for (int u = 0; u < 16; ++u) {
        float c0 = sw0[u * 16 + v];
        float c1 = sw1[u * 16 + v];
        ts += a[u] * c0;
        t0 += a[16 + u * 3 + 0] * c1;
        t1 += a[16 + u * 3 + 1] * c1;
        t2 += a[16 + u * 3 + 2] * c1;
    }
    const float S = 0.25f, EPS = 1e-8f;
    ts *= S; t0 *= S; t1 *= S; t2 *= S;

    float ns = fabsf(ts);
    float gs = ns / ((ns + EPS) * (1.0f + __expf(-ns)));
    float nv = sqrtf(t0 * t0 + t1 * t1 + t2 * t2);
    float gv = nv / ((nv + EPS) * (1.0f + __expf(-nv)));

    int base = node * 64;
    out[base + v] = nf[base + v] + ts * gs;
    out[base + 16 + v * 3 + 0] = nf[base + 16 + v * 3 + 0] + t0 * gv;
    out[base + 16 + v * 3 + 1] = nf[base + 16 + v * 3 + 1] + t1 * gv;
    out[base + 16 + v * 3 + 2] = nf[base + 16 + v * 3 + 2] + t2 * gv;
}

extern "C" void kernel_launch(void* const* d_in, const int* in_sizes, int n_in,
                              void* d_out, int out_size)
{
    const float* nf   = (const float*)d_in[0];
    const float* esh  = (const float*)d_in[1];
    const float* emb  = (const float*)d_in[2];
    const float* w1   = (const float*)d_in[3];
    const float* b1   = (const float*)d_in[4];
    const float* w2   = (const float*)d_in[5];
    const float* b2   = (const float*)d_in[6];
    const float* lw0  = (const float*)d_in[7];
    const float* lw1  = (const float*)d_in[8];
    const int*   eidx = (const int*)d_in[9];
    float* out = (float*)d_out;

    cudaFuncSetAttribute(edge_kernel, cudaFuncAttributeMaxDynamicSharedMemorySize, SMEM_TOTAL);

    zero_kernel<<<625, 1024>>>();
    edge_kernel<<<148, THREADS, SMEM_TOTAL>>>(nf, esh, emb, w1, b1, w2, b2, eidx);
    node_kernel<<<625, 256>>>(nf, lw0, lw1, out);
}

// round 12
// speedup vs baseline: 1.8448x; 1.0158x over previous
#include <cuda_runtime.h>
#include <cuda_bf16.h>
#include <cstdint>
#include <math.h>

#define NN 10000
#define EE 160000
#define TE 128
#define THREADS 512

// ---- shared memory byte offsets ----
#define SM_BHI 0         // 256 rows x 64 bf16 (128B rows), SW128
#define SM_BLO 32768
#define SM_AHI 65536     // 128 rows x 64 bf16 (128B rows), SW128
#define SM_ALO 81920
#define SM_C   98304     // 128 x 132 fp32 (padded rows) = 67584B
#define SM_XT  165888    // 64 x 128 fp32 = 32768B
#define SM_EMB 198656    // 128 x 16 fp32
#define SM_W1  206848    // 16 x 64 fp32
#define SM_B1  210944    // 64 fp32
#define SM_B2P 211200    // 256 fp32 (permuted quadrant bias)
#define SM_SH  212224    // 128 x 4 fp32
#define SM_SRC 214272    // 128 int
#define SM_DST 214784    // 128 int
#define SMEM_TOTAL 215296

#define SW128(x) ((x) ^ (((x) >> 3) & 0x70))
#define CPAD 132

__device__ float g_agg[NN * 64];

static __device__ __forceinline__ uint32_t smem_u32(const void* p) {
    uint32_t a;
    asm("{ .reg .u64 t; cvta.to.shared.u64 t, %1; cvt.u32.u64 %0, t; }" : "=r"(a) : "l"(p));
    return a;
}

#define LDSM4(r0, r1, r2, r3, addr) \
    asm volatile("ldmatrix.sync.aligned.m8n8.x4.shared.b16 {%0,%1,%2,%3}, [%4];" \
                 : "=r"(r0), "=r"(r1), "=r"(r2), "=r"(r3) : "r"(addr))

#define MMA16816(d, a, b0, b1) \
    asm volatile("mma.sync.aligned.m16n8k16.row.col.f32.bf16.bf16.f32 " \
                 "{%0,%1,%2,%3}, {%4,%5,%6,%7}, {%8,%9}, {%0,%1,%2,%3};" \
                 : "+f"((d)[0]), "+f"((d)[1]), "+f"((d)[2]), "+f"((d)[3]) \
                 : "r"((a)[0]), "r"((a)[1]), "r"((a)[2]), "r"((a)[3]), "r"(b0), "r"(b1))

__global__ __launch_bounds__(THREADS, 1)
void edge_kernel(const float* __restrict__ nf,
                 const float* __restrict__ esh,
                 const float* __restrict__ emb,
                 const float* __restrict__ w1,
                 const float* __restrict__ b1,
                 const float* __restrict__ w2,
                 const float* __restrict__ b2,
                 const int*   __restrict__ eidx)
{
    extern __shared__ __align__(1024) char sm[];
    const uint32_t sbase = smem_u32(sm);

    const int t = threadIdx.x;
    const int wid = t >> 5, lid = t & 31;
    const int qd = blockIdx.x & 3;           // v-quarter role 0..3

    float* sC   = (float*)(sm + SM_C);
    float* sXT  = (float*)(sm + SM_XT);
    float* sEmb = (float*)(sm + SM_EMB);
    float* sW1  = (float*)(sm + SM_W1);
    float* sB1  = (float*)(sm + SM_B1);
    float* sB2P = (float*)(sm + SM_B2P);
    float* sSH  = (float*)(sm + SM_SH);
    int*   sSrc = (int*)(sm + SM_SRC);
    int*   sDst = (int*)(sm + SM_DST);

    // ---- one-time staging ----
    // B physical row p = b*64 + vl*16 + u  ->  w2 col n = b*256 + u*16 + (qd*4+vl)
    for (int idx = t; idx < 64 * 256; idx += THREADS) {
        int k = idx >> 8, p = idx & 255;
        int b = p >> 6, vl = (p >> 4) & 3, u = p & 15;
        int n = b * 256 + u * 16 + qd * 4 + vl;
        float w = w2[k * 1024 + n];
        __nv_bfloat16 hi = __float2bfloat16(w);
        __nv_bfloat16 lo = __float2bfloat16(w - __bfloat162float(hi));
        uint32_t off = SW128((uint32_t)(p * 128 + k * 2));
        *(__nv_bfloat16*)(sm + SM_BHI + off) = hi;
        *(__nv_bfloat16*)(sm + SM_BLO + off) = lo;
    }
    if (t < 256) {
        int p = t;
        int b = p >> 6, vl = (p >> 4) & 3, u = p & 15;
        sB2P[p] = b2[b * 256 + u * 16 + qd * 4 + vl];
    }
    for (int i = t; i < 1024; i += THREADS) sW1[i] = w1[i];
    if (t < 64) sB1[t] = b1[t];
    __syncthreads();

    const float ALPHA = 0.17677669529663687f;   // 1/sqrt(2*16)
    const float INV3  = 0.5773502691896258f;    // 1/sqrt(3)

    // MMA warp tiling: warp tile 32e x 32p per chunk
    const int wy = wid & 3;                    // e block
    const int wx = wid >> 2;                   // p block within chunk
    const int mi = lid >> 3, r = lid & 7;
    const int a_row_base = wy * 32 + ((mi & 1) << 3) + r;
    const uint32_t a_kb = (uint32_t)((mi >> 1) << 4);
    const int b_row_off = ((mi >> 1) << 3) + r;
    const uint32_t b_kb = (uint32_t)((mi & 1) << 4);
    const uint32_t lmask = (uint32_t)(r << 4);
    const int gid = lid >> 2, tid4 = lid & 3;

    // contraction mapping: e = t&127 (warp lanes consecutive e), vl = t>>7
    const int ce = t & 127;
    const int cvl = t >> 7;

    for (int tile = blockIdx.x >> 2; tile < EE / TE; tile += 37) {
        const int e0 = tile * TE;

        // ---- phase 0: stage edge meta (overlaps prior tile's reg-only scatter) ----
        if (t < 128)      sSrc[t] = eidx[e0 + t];
        else if (t < 256) sDst[t - 128] = eidx[EE + e0 + (t - 128)];
        sSH[t] = esh[e0 * 4 + t];
        #pragma unroll
        for (int rr = 0; rr < 4; ++rr) sEmb[t + rr * THREADS] = emb[e0 * 16 + t + rr * THREADS];
        __syncthreads();                                   // barA

        // meta into registers (scatter becomes reg-only at tile end)
        const int dst = sDst[ce];
        const float sh0 = sSH[ce * 4 + 0], sh1 = sSH[ce * 4 + 1];
        const float sh2 = sSH[ce * 4 + 2], sh3 = sSH[ce * 4 + 3];

        // ---- phase 1a: stage x vectors (all 64 components) ----
        // row<16: xs[u]; row>=16: xv[u][i] at row 16 + i*16 + u
        {
            int e = t >> 2, q4 = t & 3;
            int src = sSrc[e];
            #pragma unroll
            for (int b = 0; b < 4; ++b) {
                float4 x4 = *(const float4*)(nf + src * 64 + q4 * 16 + b * 4);
                float vals[4] = {x4.x, x4.y, x4.z, x4.w};
                #pragma unroll
                for (int j = 0; j < 4; ++j) {
                    int m = q4 * 16 + b * 4 + j;           // 0..63
                    int row;
                    if (m < 16) row = m;
                    else { int mm = m - 16; row = 16 + (mm % 3) * 16 + (mm / 3); }
                    sXT[row * 128 + e] = vals[j];
                }
            }
        }

        // ---- phase 1b: H = silu(emb@w1+b1) -> bf16 hi/lo A tiles (SW128) ----
        #pragma unroll
        for (int rr = 0; rr < 8; ++rr) {
            int task = t + rr * THREADS;            // 4096 = 128e x 32 j-pairs
            int e = task >> 5, jp = task & 31;
            const float* er = sEmb + e * 16;
            float a0 = sB1[2 * jp], a1 = sB1[2 * jp + 1];
            #pragma unroll
            for (int k = 0; k < 16; ++k) {
                float ev = er[k];
                float2 wv = *(const float2*)(sW1 + k * 64 + 2 * jp);
                a0 += ev * wv.x;
                a1 += ev * wv.y;
            }
            float h0 = a0 / (1.0f + __expf(-a0));
            float h1 = a1 / (1.0f + __expf(-a1));
            __nv_bfloat16 h0h = __float2bfloat16(h0);
            __nv_bfloat16 h1h = __float2bfloat16(h1);
            __nv_bfloat16 h0l = __float2bfloat16(h0 - __bfloat162float(h0h));
            __nv_bfloat16 h1l = __float2bfloat16(h1 - __bfloat162float(h1h));
            uint32_t hi2 = (uint32_t)__bfloat16_as_ushort(h0h) |
                           ((uint32_t)__bfloat16_as_ushort(h1h) << 16);
            uint32_t lo2 = (uint32_t)__bfloat16_as_ushort(h0l) |
                           ((uint32_t)__bfloat16_as_ushort(h1l) << 16);
            uint32_t off = SW128((uint32_t)(e * 128 + jp * 4));
            *(uint32_t*)(sm + SM_AHI + off) = hi2;
            *(uint32_t*)(sm + SM_ALO + off) = lo2;
        }
        __syncthreads();                                   // barB

        float y00 = 0.0f, y01 = 0.0f;
        float z10_0 = 0.0f, z10_1 = 0.0f, z10_2 = 0.0f;
        float z11_0 = 0.0f, z11_1 = 0.0f, z11_2 = 0.0f;

        #pragma unroll 1
        for (int c = 0; c < 2; ++c) {
            const int cbase = c << 7;

            // ---- MMA chunk c ----
            float acc[2][4][4];
            #pragma unroll
            for (int m = 0; m < 2; ++m)
                #pragma unroll
                for (int nt = 0; nt < 4; ++nt)
                    #pragma unroll
                    for (int z = 0; z < 4; ++z) acc[m][nt][z] = 0.0f;

            #pragma unroll
            for (int ks = 0; ks < 4; ++ks) {
                const uint32_t kx = (uint32_t)(ks * 32);
                uint32_t ah[2][4], al[2][4], bh[2][4], bl[2][4];
                #pragma unroll
                for (int m = 0; m < 2; ++m) {
                    uint32_t row = (uint32_t)(a_row_base + m * 16);
                    uint32_t ad = sbase + SM_AHI + row * 128 + ((kx + a_kb) ^ lmask);
                    LDSM4(ah[m][0], ah[m][1], ah[m][2], ah[m][3], ad);
                    LDSM4(al[m][0], al[m][1], al[m][2], al[m][3], ad + (SM_ALO - SM_AHI));
                }
                #pragma unroll
                for (int pr = 0; pr < 2; ++pr) {
                    uint32_t p = (uint32_t)(cbase + wx * 32 + pr * 16 + b_row_off);
                    uint32_t bd = sbase + SM_BHI + p * 128 + ((kx + b_kb) ^ lmask);
                    LDSM4(bh[pr][0], bh[pr][1], bh[pr][2], bh[pr][3], bd);
                    LDSM4(bl[pr][0], bl[pr][1], bl[pr][2], bl[pr][3], bd + (SM_BLO - SM_BHI));
                }
                #pragma unroll
                for (int m = 0; m < 2; ++m)
                    #pragma unroll
                    for (int pr = 0; pr < 2; ++pr)
                        #pragma unroll
                        for (int sb = 0; sb < 2; ++sb) {
                            float* d = acc[m][pr * 2 + sb];
                            MMA16816(d, ah[m], bh[pr][sb * 2], bh[pr][sb * 2 + 1]);
                            MMA16816(d, ah[m], bl[pr][sb * 2], bl[pr][sb * 2 + 1]);
                            MMA16816(d, al[m], bh[pr][sb * 2], bh[pr][sb * 2 + 1]);
                        }
            }

            // ---- store C + bias to smem (padded rows) ----
            #pragma unroll
            for (int m = 0; m < 2; ++m)
                #pragma unroll
                for (int nt = 0; nt < 4; ++nt) {
                    int colp = wx * 32 + nt * 8 + tid4 * 2;
                    float b0 = sB2P[cbase + colp], b1v = sB2P[cbase + colp + 1];
                    int row0 = wy * 32 + m * 16 + gid;
                    float2 v01 = make_float2(acc[m][nt][0] + b0, acc[m][nt][1] + b1v);
                    float2 v23 = make_float2(acc[m][nt][2] + b0, acc[m][nt][3] + b1v);
                    *(float2*)&sC[row0 * CPAD + colp] = v01;
                    *(float2*)&sC[(row0 + 8) * CPAD + colp] = v23;
                }
            __syncthreads();                               // barC / barE

            // ---- partial contraction: chunk0 -> y00,y01; chunk1 -> z10,z11 ----
            {
                const float* cA = sC + ce * CPAD + cvl * 16;        // b = 2c
                const float* cB = cA + 64;                           // b = 2c+1
                if (c == 0) {
                    #pragma unroll
                    for (int u = 0; u < 16; ++u) {
                        float xs = sXT[u * 128 + ce];
                        y00 += xs * cA[u];
                        y01 += xs * cB[u];
                    }
                } else {
                    #pragma unroll
                    for (int u = 0; u < 16; ++u) {
                        float w10 = cA[u], w11 = cB[u];
                        float x0 = sXT[(16 + 0 * 16 + u) * 128 + ce];
                        float x1 = sXT[(16 + 1 * 16 + u) * 128 + ce];
                        float x2 = sXT[(16 + 2 * 16 + u) * 128 + ce];
                        z10_0 += x0 * w10;  z11_0 += x0 * w11;
                        z10_1 += x1 * w10;  z11_1 += x1 * w11;
                        z10_2 += x2 * w10;  z11_2 += x2 * w11;
                    }
                }
            }
            if (c == 0) __syncthreads();                   // barD (sC reuse)
        }

        // ---- combined scatter: 4 atomics per (e, v), registers only ----
        // Overlaps with next tile's phase 0 staging (no trailing barrier).
        {
            int v = qd * 4 + cvl;
            float msg_s = ALPHA * (sh0 * y00 + INV3 * (sh1 * z11_0 + sh2 * z11_1 + sh3 * z11_2));
            atomicAdd(&g_agg[dst * 64 + v], msg_s);
            atomicAdd(&g_agg[dst * 64 + 16 + v * 3 + 0], ALPHA * (y01 * sh1 + sh0 * z10_0));
            atomicAdd(&g_agg[dst * 64 + 16 + v * 3 + 1], ALPHA * (y01 * sh2 + sh0 * z10_1));
            atomicAdd(&g_agg[dst * 64 + 16 + v * 3 + 2], ALPHA * (y01 * sh3 + sh0 * z10_2));
        }
        // no barrier: scatter is reg-only; next phase 0 writes disjoint smem and
        // every smem region it touches was last read before a barrier all threads passed
    }
}

__global__ __launch_bounds__(256)
void node_kernel(const float* __restrict__ nf,
                 const float* __restrict__ lw0,
                 const float* __restrict__ lw1,
                 float* __restrict__ out)
{
    __shared__ float sw0[256], sw1[256];
    int t = threadIdx.x;
    sw0[t] = lw0[t];
    sw1[t] = lw1[t];
    __syncthreads();

    int node = blockIdx.x * 16 + (t >> 4);
    int v = t & 15;
    float* a = g_agg + node * 64;

    float ts = 0.0f, t0 = 0.0f, t1 = 0.0f, t2 = 0.0f;
    #pragma unroll
    for (int u = 0; u < 16; ++u) {
        float c0 = sw0[u * 16 + v];
        float c1 = sw1[u * 16 + v];
        ts += a[u] * c0;
        t0 += a[16 + u * 3 + 0] * c1;
        t1 += a[16 + u * 3 + 1] * c1;
        t2 += a[16 + u * 3 + 2] * c1;
    }
    __syncthreads();   // all threads of this block (covering these 16 nodes) done reading
    // re-zero this node's slots for the next graph replay (g_agg starts zeroed at load)
    a[v] = 0.0f;
    a[16 + v * 3 + 0] = 0.0f;
    a[16 + v * 3 + 1] = 0.0f;
    a[16 + v * 3 + 2] = 0.0f;

    const float S = 0.25f, EPS = 1e-8f;
    ts *= S; t0 *= S; t1 *= S; t2 *= S;

    float ns = fabsf(ts);
    float gs = ns / ((ns + EPS) * (1.0f + __expf(-ns)));
    float nv = sqrtf(t0 * t0 + t1 * t1 + t2 * t2);
    float gv = nv / ((nv + EPS) * (1.0f + __expf(-nv)));

    int base = node * 64;
    out[base + v] = nf[base + v] + ts * gs;
    out[base + 16 + v * 3 + 0] = nf[base + 16 + v * 3 + 0] + t0 * gv;
    out[base + 16 + v * 3 + 1] = nf[base + 16 + v * 3 + 1] + t1 * gv;
    out[base + 16 + v * 3 + 2] = nf[base + 16 + v * 3 + 2] + t2 * gv;
}

extern "C" void kernel_launch(void* const* d_in, const int* in_sizes, int n_in,
                              void* d_out, int out_size)
{
    const float* nf   = (const float*)d_in[0];
    const float* esh  = (const float*)d_in[1];
    const float* emb  = (const float*)d_in[2];
    const float* w1   = (const float*)d_in[3];
    const float* b1   = (const float*)d_in[4];
    const float* w2   = (const float*)d_in[5];
    const float* b2   = (const float*)d_in[6];
    const float* lw0  = (const float*)d_in[7];
    const float* lw1  = (const float*)d_in[8];
    const int*   eidx = (const int*)d_in[9];
    float* out = (float*)d_out;

    cudaFuncSetAttribute(edge_kernel, cudaFuncAttributeMaxDynamicSharedMemorySize, SMEM_TOTAL);

    // g_agg: zeroed at module load; node_kernel re-zeros after reading each call.
    edge_kernel<<<148, THREADS, SMEM_TOTAL>>>(nf, esh, emb, w1, b1, w2, b2, eidx);
    node_kernel<<<625, 256>>>(nf, lw0, lw1, out);
}